// round 10
// baseline (speedup 1.0000x reference)
#include <cuda_runtime.h>

#define THREADS 128
#define ROWS    64

// Prep block layout (floats) — identical in gPrep and shared memory:
#define OFF_WT   0        // 64 x 64  Wt[k][i]
#define OFF_GT   4096     // 64 x 64  Gt[k][i]
#define OFF_M    8192     // 64 x 64  M[k][l]
#define OFF_B    12288
#define OFF_WY   12352
#define OFF_wy   12416
#define OFF_wlt  12480
#define OFF_wys  12544
#define OFF_MISC 12608    // [0]=wl[64]
#define PREP_FLOATS 12624

// shared-only extras
#define OFF_RED  12624    // 4 warps x 2
#define OFF_PART 12632    // 3 partner warps x 3 vals x 64 rows = 576
#define OFF_FLAG 13208
#define OFF_X    13212    // input stage, 64 x 65 (stride 65 -> conflict-free)
#define OFF_S    17372    // s values,    64 x 65
#define SMEM_FLOATS 21532
#define SMEM_BYTES  (SMEM_FLOATS * 4)

// ---- persistent device scratch ----
__device__ float        gPrep[PREP_FLOATS];
__device__ float        gPartI[512];
__device__ float        gPartN[512];
__device__ unsigned int gCount = 0;

__device__ __forceinline__ int pair_off(int i) {
    return 129 + i * (2 * 129 - i - 1) / 2;
}
__device__ __forceinline__ unsigned long long packpair(float a, float b) {
    unsigned long long r;
    asm("mov.b64 %0, {%1, %2};" : "=l"(r) : "f"(a), "f"(b));
    return r;
}
__device__ __forceinline__ void unpack2(unsigned long long v, float& a, float& b) {
    asm("mov.b64 {%0, %1}, %2;" : "=f"(a), "=f"(b) : "l"(v));
}
#define FMA2(acc, a, b) asm("fma.rn.f32x2 %0, %1, %2, %0;" : "+l"(acc) : "l"(a), "l"(b))

__device__ __forceinline__ float red2(unsigned long long v) {
    float a, b;
    unpack2(v, a, b);
    return a + b;
}

__device__ __forceinline__ float tanh_fast(float w) {
    float e, r;
    asm("ex2.approx.f32 %0, %1;" : "=f"(e) : "f"(w * 2.885390081777927f));
    asm("rcp.approx.f32 %0, %1;" : "=f"(r) : "f"(e + 1.0f));
    return fmaf(-2.0f, r, 1.0f);
}

// ---------------------------------------------------------------------------
__global__ void prep_kernel(const float* __restrict__ tw,
                            const float* __restrict__ tb,
                            const float* __restrict__ mw) {
    int tid = blockIdx.x * blockDim.x + threadIdx.x;
    if (tid >= PREP_FLOATS) return;
    float v = 0.0f;
    if (tid < 4096) {                       // Wt[k][i]
        int k = tid >> 6, i = tid & 63;
        v = tw[k * 65 + i];
    } else if (tid < 8192) {                // Gt[k][i]
        int idx = tid - 4096;
        int k = idx >> 6, i = idx & 63;
        v = mw[pair_off(i) + 64 + k - i];
    } else if (tid < 12288) {               // M[k][l]
        int idx = tid - 8192;
        int k = idx >> 6, l = idx & 63;
        if (k != l) {
            int a = k < l ? k : l;
            int b = k < l ? l : k;
            v = 0.5f * mw[pair_off(65 + a) + b - a - 1];
        }
    } else if (tid < 12352) {
        v = tb[tid - 12288];
    } else if (tid < 12416) {
        int k = tid - 12352;
        v = tw[k * 65 + 64];
    } else if (tid < 12480) {
        int i = tid - 12416;
        v = mw[pair_off(i) + 63 - i];
    } else if (tid < 12544) {
        v = mw[65 + (tid - 12480)];
    } else if (tid < 12608) {
        v = mw[pair_off(64) + (tid - 12544)];
    } else if (tid == 12608) {
        v = mw[64];
    }
    gPrep[tid] = v;
    if (tid == 0) gCount = 0;
}

// ---------------------------------------------------------------------------
// 128 threads: warp = k-quarter (16 k's, warp-uniform weight reads),
// lane = row-pair (rows lane, lane+32). Per-k immediate reduction keeps
// register pressure low so ptxas can batch shared loads.
// ---------------------------------------------------------------------------
__global__ void __launch_bounds__(THREADS, 2)
fused_kernel(const float* __restrict__ inps,
             float* __restrict__ out,
             int Bn) {
    extern __shared__ float sm[];
    const int t    = threadIdx.x;
    const int lane = t & 31;
    const int q    = t >> 5;
    const int kb   = q * 16;
    const int rA   = lane;
    const int rB   = lane + 32;
    const int row0 = blockIdx.x * ROWS;

    // coalesced weight copy
    {
        const float4* src = reinterpret_cast<const float4*>(gPrep);
        float4* dst = reinterpret_cast<float4*>(sm);
        for (int idx = t; idx < PREP_FLOATS / 4; idx += THREADS)
            dst[idx] = src[idx];
    }
    // coalesced input stage
    {
        const float4* src = reinterpret_cast<const float4*>(inps + (long)row0 * 65);
        float4* dst = reinterpret_cast<float4*>(sm + OFF_X);
        for (int idx = t; idx < (ROWS * 65) / 4; idx += THREADS)
            dst[idx] = src[idx];
    }
    __syncthreads();

    const float* XA = sm + OFF_X + rA * 65;
    const float* XB = sm + OFF_X + rB * 65;
    float* SA = sm + OFF_S + rA * 65;
    float* SB = sm + OFF_S + rB * 65;
    const float yA = XA[64];
    const float yB = XB[64];

    float accXW_A = 0.0f, accXW_B = 0.0f;
    if (q == 0) {
#pragma unroll 8
        for (int i = 0; i < 64; i++) {
            float w = sm[OFF_wy + i];
            accXW_A = fmaf(XA[i], w, accXW_A);
            accXW_B = fmaf(XB[i], w, accXW_B);
        }
    }

    // ---- Phase 1: c = x.Wt, a = x.Gt (shared x packs, per-k reduce) ----
    float cvA[16], cvB[16], avA[16], avB[16];
#pragma unroll
    for (int kk = 0; kk < 16; kk++) { cvA[kk] = 0.0f; cvB[kk] = 0.0f; avA[kk] = 0.0f; avB[kk] = 0.0f; }

#pragma unroll
    for (int half = 0; half < 2; half++) {
        unsigned long long xa[16], xb[16];
#pragma unroll
        for (int j = 0; j < 16; j++) {
            xa[j] = packpair(XA[32 * half + 2 * j], XA[32 * half + 2 * j + 1]);
            xb[j] = packpair(XB[32 * half + 2 * j], XB[32 * half + 2 * j + 1]);
        }
#pragma unroll
        for (int kk = 0; kk < 16; kk++) {
            int k = kb + kk;
            const ulonglong2* pW = reinterpret_cast<const ulonglong2*>(sm + OFF_WT + k * 64 + 32 * half);
            const ulonglong2* pG = reinterpret_cast<const ulonglong2*>(sm + OFF_GT + k * 64 + 32 * half);
            unsigned long long cA = 0ULL, cB = 0ULL, aA = 0ULL, aB = 0ULL;
            unsigned long long cA2 = 0ULL, cB2 = 0ULL, aA2 = 0ULL, aB2 = 0ULL;
#pragma unroll
            for (int jj = 0; jj < 8; jj += 2) {
                ulonglong2 W0 = pW[jj], W1 = pW[jj + 1];
                ulonglong2 G0 = pG[jj], G1 = pG[jj + 1];
                int xi = 2 * jj;
                FMA2(cA,  xa[xi],     W0.x);  FMA2(cA,  xa[xi + 1], W0.y);
                FMA2(cA2, xa[xi + 2], W1.x);  FMA2(cA2, xa[xi + 3], W1.y);
                FMA2(cB,  xb[xi],     W0.x);  FMA2(cB,  xb[xi + 1], W0.y);
                FMA2(cB2, xb[xi + 2], W1.x);  FMA2(cB2, xb[xi + 3], W1.y);
                FMA2(aA,  xa[xi],     G0.x);  FMA2(aA,  xa[xi + 1], G0.y);
                FMA2(aA2, xa[xi + 2], G1.x);  FMA2(aA2, xa[xi + 3], G1.y);
                FMA2(aB,  xb[xi],     G0.x);  FMA2(aB,  xb[xi + 1], G0.y);
                FMA2(aB2, xb[xi + 2], G1.x);  FMA2(aB2, xb[xi + 3], G1.y);
            }
            cvA[kk] += red2(cA) + red2(cA2);
            cvB[kk] += red2(cB) + red2(cB2);
            avA[kk] += red2(aA) + red2(aA2);
            avB[kk] += red2(aB) + red2(aB2);
        }
    }

    // ---- epilogue: tanh, d/s, penalties, gz += d.a ----
    float dA[16], dB[16];
    float dwA = 0.0f, dwB = 0.0f, swA = 0.0f, swB = 0.0f;
    float gzA = 0.0f, gzB = 0.0f, accI = 0.0f, accN = 0.0f;
#pragma unroll
    for (int kk = 0; kk < 16; kk++) {
        int k = kb + kk;
        float bk  = sm[OFF_B + k];
        float wyk = sm[OFF_WY + k];
        float wlt = sm[OFF_wlt + k];
        float wys = sm[OFF_wys + k];

        float cv = cvA[kk] + bk;
        float hv = yA * wyk;
        float w1 = cv + hv, w2 = cv - hv;
        float t1 = tanh_fast(w1), t2 = tanh_fast(w2);
        float dk = t1 - t2, sk = t1 + t2;
        dA[kk] = dk;
        SA[k]  = sk;
        gzA = fmaf(dk, avA[kk], gzA);
        dwA = fmaf(dk, wlt, dwA);
        swA = fmaf(sk, wys, swA);
        float e1 = fmaf(-t1, t1, 1.0f), e2 = fmaf(-t2, t2, 1.0f);
        accI = fmaf(e1, e1, accI);
        accI = fmaf(e2, e2, accI);
        float nt = fmaf(t2, w2, -(t1 * w1));
        accN = fmaf(nt, nt, accN);

        cv = cvB[kk] + bk;
        hv = yB * wyk;
        w1 = cv + hv; w2 = cv - hv;
        t1 = tanh_fast(w1); t2 = tanh_fast(w2);
        dk = t1 - t2; sk = t1 + t2;
        dB[kk] = dk;
        SB[k]  = sk;
        gzB = fmaf(dk, avB[kk], gzB);
        dwB = fmaf(dk, wlt, dwB);
        swB = fmaf(sk, wys, swB);
        e1 = fmaf(-t1, t1, 1.0f); e2 = fmaf(-t2, t2, 1.0f);
        accI = fmaf(e1, e1, accI);
        accI = fmaf(e2, e2, accI);
        nt = fmaf(t2, w2, -(t1 * w1));
        accN = fmaf(nt, nt, accN);
    }

    __syncthreads();   // all s written

    // ---- Phase 2: gz += d^T M s (per-k reduce) ----
#pragma unroll
    for (int half = 0; half < 2; half++) {
        unsigned long long sa[16], sb[16];
#pragma unroll
        for (int j = 0; j < 16; j++) {
            sa[j] = packpair(SA[32 * half + 2 * j], SA[32 * half + 2 * j + 1]);
            sb[j] = packpair(SB[32 * half + 2 * j], SB[32 * half + 2 * j + 1]);
        }
#pragma unroll
        for (int kk = 0; kk < 16; kk++) {
            int k = kb + kk;
            const ulonglong2* pM = reinterpret_cast<const ulonglong2*>(sm + OFF_M + k * 64 + 32 * half);
            unsigned long long mA = 0ULL, mB = 0ULL, mA2 = 0ULL, mB2 = 0ULL;
#pragma unroll
            for (int jj = 0; jj < 8; jj += 2) {
                ulonglong2 M0 = pM[jj], M1 = pM[jj + 1];
                int xi = 2 * jj;
                FMA2(mA,  sa[xi],     M0.x);  FMA2(mA,  sa[xi + 1], M0.y);
                FMA2(mA2, sa[xi + 2], M1.x);  FMA2(mA2, sa[xi + 3], M1.y);
                FMA2(mB,  sb[xi],     M0.x);  FMA2(mB,  sb[xi + 1], M0.y);
                FMA2(mB2, sb[xi + 2], M1.x);  FMA2(mB2, sb[xi + 3], M1.y);
            }
            gzA = fmaf(dA[kk], red2(mA) + red2(mA2), gzA);
            gzB = fmaf(dB[kk], red2(mB) + red2(mB2), gzB);
        }
    }

    // ---- combine the 4 k-quarter warps ----
    if (q != 0) {
        int p = OFF_PART + (q - 1) * 192;
        sm[p + rA]       = gzA;  sm[p + rB]       = gzB;
        sm[p + 64 + rA]  = dwA;  sm[p + 64 + rB]  = dwB;
        sm[p + 128 + rA] = swA;  sm[p + 128 + rB] = swB;
    }
    __syncthreads();
    if (q == 0) {
#pragma unroll
        for (int p = 0; p < 3; p++) {
            int b = OFF_PART + p * 192;
            gzA += sm[b + rA];       gzB += sm[b + rB];
            dwA += sm[b + 64 + rA];  dwB += sm[b + 64 + rB];
            swA += sm[b + 128 + rA]; swB += sm[b + 128 + rB];
        }
        float wl64 = sm[OFF_MISC];
        out[row0 + rA] = 1.0f + 2.0f * yA * wl64 + dwA + 2.0f * yA * accXW_A + yA * swA + gzA;
        out[row0 + rB] = 1.0f + 2.0f * yB * wl64 + dwB + 2.0f * yB * accXW_B + yB * swB + gzB;
    }

    // ---- penalty reduction ----
#pragma unroll
    for (int off = 16; off > 0; off >>= 1) {
        accI += __shfl_xor_sync(0xffffffffu, accI, off);
        accN += __shfl_xor_sync(0xffffffffu, accN, off);
    }
    if (lane == 0) {
        sm[OFF_RED + q]     = accI;
        sm[OFF_RED + 4 + q] = accN;
    }
    __syncthreads();
    if (t == 0) {
        float pI = 0.0f, pN = 0.0f;
#pragma unroll
        for (int w = 0; w < 4; w++) { pI += sm[OFF_RED + w]; pN += sm[OFF_RED + 4 + w]; }
        gPartI[blockIdx.x] = pI;
        gPartN[blockIdx.x] = pN;
        __threadfence();
        unsigned int tk = atomicAdd(&gCount, 1u);
        sm[OFF_FLAG] = (tk == gridDim.x - 1) ? 1.0f : 0.0f;
    }
    __syncthreads();

    if (sm[OFF_FLAG] != 0.0f && t < 32) {
        __threadfence();
        double sI = 0.0, sN = 0.0;
        for (int i = t; i < (int)gridDim.x; i += 32) {
            sI += (double)gPartI[i];
            sN += (double)gPartN[i];
        }
#pragma unroll
        for (int off = 16; off > 0; off >>= 1) {
            sI += __shfl_xor_sync(0xffffffffu, sI, off);
            sN += __shfl_xor_sync(0xffffffffu, sN, off);
        }
        if (t == 0) {
            out[Bn]     = (float)(sI * (1.0 / 300.0));
            out[Bn + 1] = (float)sN;
            gCount = 0;   // reset for next graph replay
        }
    }
}

extern "C" void kernel_launch(void* const* d_in, const int* in_sizes, int n_in,
                              void* d_out, int out_size) {
    const float* inps = (const float*)d_in[0];
    const float* tw   = (const float*)d_in[1];
    const float* tb   = (const float*)d_in[2];
    const float* mw   = (const float*)d_in[3];
    float* out = (float*)d_out;

    int Bn = in_sizes[0] / 65;

    cudaFuncSetAttribute(fused_kernel,
                         cudaFuncAttributeMaxDynamicSharedMemorySize, SMEM_BYTES);

    prep_kernel<<<(PREP_FLOATS + 255) / 256, 256>>>(tw, tb, mw);
    fused_kernel<<<Bn / ROWS, THREADS, SMEM_BYTES>>>(inps, out, Bn);
}